// round 8
// baseline (speedup 1.0000x reference)
#include <cuda_runtime.h>

// LIF scan, exact two-phase checkpointing, v3 (explicit setp/selp chain).
// B=16, S=256, H=128, N=64.  T = S*H = 32768 steps per (b,n) chain.
//
// Phase 1 (lif_prepass): serial state-only chain. Two warps per CTA:
//   warp0 runs the recurrence reading x from smem (broadcast LDS, fully
//   latency-covered), warp1 prefetches x in 8-row double-buffered blocks.
//   Records the TRUE carried state every 8 s-rows (32 checkpoints/chain).
//   Chain step forced to FADD || FSETP -> FSEL (pred-as-data) via PTX:
//       t  = v + x         (parallel with setp)
//       p  = (v <= thr)
//       v' = selp(t, x, p)   // fl(0 + x) == x exactly
//   Critical path ~8 cyc/step (vs 10 for the cross-pipe FSET->FFMA form).
//
// Phase 2 (lif_output): 1024 independent CTAs replay one 8-row block each
//   from its exact checkpoint (R6-proven FSET->FFMA form, identical value
//   sequence); smem-transpose producer/flusher pair gives fully coalesced
//   512B stores of outs + synthesized spikes.

#define BB 16
#define SS 256
#define HH 128
#define NN 64
#define TT (SS * HH)

#define BLKROWS 8              // s-rows per block (1024 steps)
#define NBLK (SS / BLKROWS)    // 32 checkpoints per chain
#define ROWPAD 132             // conflict-free float4 staging stride

static const size_t BSNH = (size_t)BB * SS * NN * HH;  // 33,554,432

// True chain states at block boundaries (carried v = post-add accumulator).
__device__ float g_chk[NBLK][BB][NN];

__device__ __forceinline__ float set_le(float a, float b) {
    float r; asm("set.le.f32.f32 %0, %1, %2;" : "=f"(r) : "f"(a), "f"(b)); return r;
}

// Chain step: forced FADD || FSETP -> FSEL (selp). Bit-identical to the
// reference sequential order (reset folds into selecting the bare x).
__device__ __forceinline__ float lif_step(float v, float thr, float x) {
    float r;
    asm("{\n\t"
        ".reg .pred p;\n\t"
        ".reg .f32 t;\n\t"
        "add.f32 t, %1, %3;\n\t"
        "setp.le.f32 p, %1, %2;\n\t"
        "selp.f32 %0, t, %3, p;\n\t"
        "}"
        : "=f"(r) : "f"(v), "f"(thr), "f"(x));
    return r;
}

// Output-phase step (R6-proven; identical value trajectory to lif_step).
#define OUT_STEP(XC, OC) do {               \
    float _m = set_le(v, thr);              \
    v = __fmaf_rn(v, _m, (XC));             \
    (OC) = (v > thr) ? v : 0.0f;            \
} while (0)

// ---------------------------------------------------------------------------
// Phase 1: serial state chain with dedicated x-prefetch warp.
// grid = 32 (b, neuron-half), block = 64.
// ---------------------------------------------------------------------------
__global__ void __launch_bounds__(64, 1)
lif_prepass(const float* __restrict__ x,       // [B, S, H]
            const float* __restrict__ thresh,  // [N]
            const float* __restrict__ acc0)    // [B, N]
{
    __shared__ float xsh[2][BLKROWS * HH + 4];   // two 4KB x blocks + pad

    const int tid  = threadIdx.x;
    const int wid  = tid >> 5;
    const int lane = tid & 31;
    const int b    = blockIdx.x >> 1;
    const int half = blockIdx.x & 1;

    const float4* __restrict__ xg = (const float4*)(x + (size_t)b * TT);
    const int CHUNKS = BLKROWS * (HH / 4);       // 256 float4 per block

    if (wid == 1) {                              // preload block 0
        #pragma unroll
        for (int i = lane; i < CHUNKS; i += 32)
            ((float4*)xsh[0])[i] = xg[i];
    }
    __syncthreads();

    if (wid == 0) {
        // -------- chain warp: 32 neurons of (b, half) --------
        const int n = half * 32 + lane;
        const float thr = thresh[n];
        float v = acc0[b * NN + n];

        for (int blk = 0; blk < NBLK; ++blk) {
            g_chk[blk][b][n] = v;                // true state entering block

            const float4* xs4 = (const float4*)xsh[blk & 1];
            float4 xv = xs4[0];
            #pragma unroll 8
            for (int q = 0; q < CHUNKS; ++q) {
                float4 xn = xs4[q + 1];          // broadcast LDS, pad-covered
                v = lif_step(v, thr, xv.x);
                v = lif_step(v, thr, xv.y);
                v = lif_step(v, thr, xv.z);
                v = lif_step(v, thr, xv.w);
                xv = xn;
            }
            __syncthreads();                     // block consumed; next ready
        }
    } else {
        // -------- loader warp: one block ahead --------
        for (int blk = 0; blk < NBLK; ++blk) {
            if (blk + 1 < NBLK) {
                const float4* src = xg + (size_t)(blk + 1) * CHUNKS;
                float4* dst = (float4*)xsh[(blk + 1) & 1];
                #pragma unroll
                for (int i = lane; i < CHUNKS; i += 32)
                    dst[i] = src[i];
            }
            __syncthreads();
        }
    }
}

// ---------------------------------------------------------------------------
// Phase 2: parallel block replay with coalesced output (unchanged from R6,
// measured 64us / 41% DRAM).
// grid = B * 2 * NBLK = 1024, block = 64 (warp0 producer, warp1 flusher).
// ---------------------------------------------------------------------------
__global__ void __launch_bounds__(64, 1)
lif_output(const float* __restrict__ x,
           const float* __restrict__ thresh,
           float* __restrict__ outbuf,
           int write_spikes)
{
    __shared__ float sbuf[2][32 * ROWPAD];

    const int tid  = threadIdx.x;
    const int sblk = blockIdx.x & (NBLK - 1);
    const int half = (blockIdx.x >> 5) & 1;
    const int b    = blockIdx.x >> 6;
    const int n0   = half * 32;
    const int s0   = sblk * BLKROWS;

    if (tid < 32) {
        // ---------------- producer: exact replay from checkpoint ---------
        const int lane = tid;
        const int n    = n0 + lane;
        const float thr = thresh[n];
        float v = g_chk[sblk][b][n];

        const float4* __restrict__ xp =
            (const float4*)(x + (size_t)b * TT + (size_t)s0 * HH);

        float* const row0 = &sbuf[0][lane * ROWPAD];
        float* const row1 = &sbuf[1][lane * ROWPAD];

        for (int r = 0; r < BLKROWS; ++r) {
            float* rw = (r & 1) ? row1 : row0;
            const float4* xrow = xp + r * (HH / 4);
            #pragma unroll 8
            for (int q = 0; q < HH / 4; ++q) {
                float4 xv = xrow[q];             // broadcast LDG.128
                float4 o;
                OUT_STEP(xv.x, o.x); OUT_STEP(xv.y, o.y);
                OUT_STEP(xv.z, o.z); OUT_STEP(xv.w, o.w);
                *(float4*)&rw[q * 4] = o;        // conflict-free STS.128
            }
            __syncthreads();                     // row r staged
        }
    } else {
        // ---------------- flusher: transpose + spikes --------------------
        const int lane = tid - 32;
        float* __restrict__ outp = outbuf;
        float* __restrict__ spkp = outbuf + BSNH;

        for (int r = 0; r < BLKROWS; ++r) {
            __syncthreads();                     // wait for row r
            const float* buf = sbuf[r & 1];
            const int s = s0 + r;
            size_t base = (((size_t)b * SS + s) * NN + n0) * HH + lane * 4;
            #pragma unroll 4
            for (int rr = 0; rr < 32; ++rr) {
                float4 vv = *(const float4*)&buf[rr * ROWPAD + lane * 4];
                *(float4*)&outp[base + (size_t)rr * HH] = vv;  // 512B coalesced
                if (write_spikes) {
                    float4 sp;
                    sp.x = (vv.x > 0.0f) ? 1.0f : 0.0f;
                    sp.y = (vv.y > 0.0f) ? 1.0f : 0.0f;
                    sp.z = (vv.z > 0.0f) ? 1.0f : 0.0f;
                    sp.w = (vv.w > 0.0f) ? 1.0f : 0.0f;
                    *(float4*)&spkp[base + (size_t)rr * HH] = sp;
                }
            }
        }
    }
}

extern "C" void kernel_launch(void* const* d_in, const int* in_sizes, int n_in,
                              void* d_out, int out_size)
{
    const float* x      = (const float*)d_in[0];  // [16, 256, 128] f32
    const float* thresh = (const float*)d_in[1];  // [64] f32
    const float* acc0   = (const float*)d_in[2];  // [16, 64] f32
    float* out = (float*)d_out;

    int write_spikes = ((size_t)out_size >= 2 * BSNH) ? 1 : 0;

    lif_prepass<<<BB * 2, 64>>>(x, thresh, acc0);
    lif_output<<<BB * 2 * NBLK, 64>>>(x, thresh, out, write_spikes);
}

// round 9
// speedup vs baseline: 1.7563x; 1.7563x over previous
#include <cuda_runtime.h>

// LIF scan — fused chain + overlapped block replay (R7 structure, R6 chain).
// B=16, S=256, H=128, N=64.  T = S*H = 32768 steps per (b,n) chain.
//
// Grid = 32 chain CTAs (blockIdx 0..31) + 1024 output CTAs, one launch.
//  * Chain CTA (b, half): warp0 runs the serial recurrence reading x from a
//    smem double buffer (warp1 prefetches 8-row blocks), at the measured
//    ~10 cyc/step FSET->FFMA form. Publishes the TRUE carried state entering
//    each 8-row block (release fence + flag).
//  * Output CTA (sblk, grp): spin-waits for its flag, replays its 1024 steps
//    from the exact checkpoint, streams outs + synthesized spikes through a
//    smem transpose for coalesced 512B stores (measured 59us / 45% DRAM).
//  * Reset kernel clears flags first (they persist across graph replays).
//
// Step math (bit-identical to reference sequential order; both phases
// produce identical value sequences — validated rel_err 0.0 in R4/R6/R7/R8):
//   m = (v <= thr) ? 1.0f : 0.0f   (FSET)
//   v = fmaf(v, m, x)              (fma(v,1,x)==fl(v+x); fma(v,0,x)==x)
//   out = (v > thr) ? v : 0.0f     (off-chain)

#define BB 16
#define SS 256
#define HH 128
#define NN 64
#define TT (SS * HH)

#define BLKROWS 8
#define NBLK (SS / BLKROWS)           // 32
#define ROWPAD 132
#define NGRP 32                       // (b, neuron-half)
#define NCHAIN NGRP
#define CHUNKS (BLKROWS * (HH / 4))   // 256 float4 per 8-row block

static const size_t BSNH = (size_t)BB * SS * NN * HH;

__device__ float g_chk[NBLK][BB][NN];
__device__ int   g_flag[NBLK][NGRP];

__device__ __forceinline__ float set_le(float a, float b) {
    float r; asm("set.le.f32.f32 %0, %1, %2;" : "=f"(r) : "f"(a), "f"(b)); return r;
}

#define CHAIN_STEP(XC) do {                 \
    float _m = set_le(v, thr);              \
    v = __fmaf_rn(v, _m, (XC));             \
} while (0)

#define OUT_STEP(XC, OC) do {               \
    float _m = set_le(v, thr);              \
    v = __fmaf_rn(v, _m, (XC));             \
    (OC) = (v > thr) ? v : 0.0f;            \
} while (0)

__global__ void lif_reset()
{
    int i = threadIdx.x;
    if (i < NBLK * NGRP) ((int*)g_flag)[i] = 0;
}

__global__ void __launch_bounds__(64, 1)
lif_fused(const float* __restrict__ x,       // [B, S, H]
          const float* __restrict__ thresh,  // [N]
          const float* __restrict__ acc0,    // [B, N]
          float* __restrict__ outbuf,        // outs | spikes
          int write_spikes)
{
    // Union of the two roles' shared memory needs.
    __shared__ float smem_raw[2 * 32 * ROWPAD];

    const int tid  = threadIdx.x;
    const int lane = tid & 31;

    if (blockIdx.x < NCHAIN) {
        // ================== CHAIN CTA ==================
        const int grp  = blockIdx.x;
        const int b    = grp >> 1;
        const int half = grp & 1;
        const int wid  = tid >> 5;

        float (*xsh)[BLKROWS * HH + 4] = (float (*)[BLKROWS * HH + 4])smem_raw;
        const float4* __restrict__ xg = (const float4*)(x + (size_t)b * TT);

        if (wid == 1) {                       // preload block 0
            #pragma unroll
            for (int i = lane; i < CHUNKS; i += 32)
                ((float4*)xsh[0])[i] = xg[i];
        }
        __syncthreads();

        if (wid == 0) {
            const int n = half * 32 + lane;
            const float thr = thresh[n];
            float v = acc0[b * NN + n];

            for (int blk = 0; blk < NBLK; ++blk) {
                // Publish checkpoint (state entering block blk), release.
                g_chk[blk][b][n] = v;
                __threadfence();
                if (lane == 0) g_flag[blk][grp] = 1;

                const float4* xs4 = (const float4*)xsh[blk & 1];
                float4 xv = xs4[0];
                #pragma unroll 8
                for (int q = 0; q < CHUNKS; ++q) {
                    float4 xn = xs4[q + 1];   // broadcast LDS, pad-covered
                    CHAIN_STEP(xv.x); CHAIN_STEP(xv.y);
                    CHAIN_STEP(xv.z); CHAIN_STEP(xv.w);
                    xv = xn;
                }
                __syncthreads();              // block consumed; next staged
            }
        } else {
            for (int blk = 0; blk < NBLK; ++blk) {
                if (blk + 1 < NBLK) {
                    const float4* src = xg + (size_t)(blk + 1) * CHUNKS;
                    float4* dst = (float4*)xsh[(blk + 1) & 1];
                    #pragma unroll
                    for (int i = lane; i < CHUNKS; i += 32)
                        dst[i] = src[i];
                }
                __syncthreads();
            }
        }
    } else {
        // ================== OUTPUT CTA ==================
        const int cidx = blockIdx.x - NCHAIN;
        const int grp  = cidx & (NGRP - 1);   // grp varies fastest
        const int sblk = cidx >> 5;           // low blocks first
        const int b    = grp >> 1;
        const int n0   = (grp & 1) * 32;
        const int s0   = sblk * BLKROWS;

        float (*sbuf)[32 * ROWPAD] = (float (*)[32 * ROWPAD])smem_raw;

        // Wait for this block's checkpoint (acquire).
        if (tid == 0) {
            const volatile int* f = &g_flag[sblk][grp];
            while (*f == 0) __nanosleep(128);
        }
        __syncthreads();
        __threadfence();

        if (tid < 32) {
            // -------- producer: exact replay from checkpoint --------
            const int n = n0 + lane;
            const float thr = thresh[n];
            float v = g_chk[sblk][b][n];

            const float4* __restrict__ xp =
                (const float4*)(x + (size_t)b * TT + (size_t)s0 * HH);

            float* const row0 = &sbuf[0][lane * ROWPAD];
            float* const row1 = &sbuf[1][lane * ROWPAD];

            for (int r = 0; r < BLKROWS; ++r) {
                float* rw = (r & 1) ? row1 : row0;
                const float4* xrow = xp + r * (HH / 4);
                #pragma unroll 8
                for (int q = 0; q < HH / 4; ++q) {
                    float4 xv = xrow[q];      // broadcast LDG (L2-hot)
                    float4 o;
                    OUT_STEP(xv.x, o.x); OUT_STEP(xv.y, o.y);
                    OUT_STEP(xv.z, o.z); OUT_STEP(xv.w, o.w);
                    *(float4*)&rw[q * 4] = o;
                }
                __syncthreads();
            }
        } else {
            // -------- flusher: transpose + spikes --------
            const int fl = tid - 32;
            float* __restrict__ outp = outbuf;
            float* __restrict__ spkp = outbuf + BSNH;

            for (int r = 0; r < BLKROWS; ++r) {
                __syncthreads();
                const float* buf = sbuf[r & 1];
                const int s = s0 + r;
                size_t base = (((size_t)b * SS + s) * NN + n0) * HH + fl * 4;
                #pragma unroll 4
                for (int rr = 0; rr < 32; ++rr) {
                    float4 vv = *(const float4*)&buf[rr * ROWPAD + fl * 4];
                    *(float4*)&outp[base + (size_t)rr * HH] = vv;
                    if (write_spikes) {
                        float4 sp;
                        sp.x = (vv.x > 0.0f) ? 1.0f : 0.0f;
                        sp.y = (vv.y > 0.0f) ? 1.0f : 0.0f;
                        sp.z = (vv.z > 0.0f) ? 1.0f : 0.0f;
                        sp.w = (vv.w > 0.0f) ? 1.0f : 0.0f;
                        *(float4*)&spkp[base + (size_t)rr * HH] = sp;
                    }
                }
            }
        }
    }
}

extern "C" void kernel_launch(void* const* d_in, const int* in_sizes, int n_in,
                              void* d_out, int out_size)
{
    const float* x      = (const float*)d_in[0];  // [16, 256, 128] f32
    const float* thresh = (const float*)d_in[1];  // [64] f32
    const float* acc0   = (const float*)d_in[2];  // [16, 64] f32
    float* out = (float*)d_out;

    int write_spikes = ((size_t)out_size >= 2 * BSNH) ? 1 : 0;

    lif_reset<<<1, 1024>>>();
    lif_fused<<<NCHAIN + NGRP * NBLK, 64>>>(x, thresh, acc0, out, write_spikes);
}

// round 12
// speedup vs baseline: 1.7633x; 1.0040x over previous
#include <cuda_runtime.h>

// LIF scan — fused chain + overlapped block replay, v2.
// B=16, S=256, H=128, N=64.  T = S*H = 32768 steps per (b,n) chain.
//
// R10 changes vs R9 (198.6us):
//  1. Per-lane release/acquire checkpoint flags (st.release.gpu /
//     ld.acquire.gpu) — removes the per-block __threadfence (gpu membar)
//     from the chain's critical path.
//  2. Static smem padded to 48KB -> max 4 CTAs/SM, so a chain CTA shares
//     SMSP0 with at most 3 output producer warps instead of 5.
//  3. Output producers spin per-lane; no preamble barrier.
//
// Step math (bit-identical to reference order; validated rel_err 0.0
// in R4/R6/R7/R8/R9):
//   m = (v <= thr) ? 1.0f : 0.0f   (FSET)
//   v = fmaf(v, m, x)              (fma(v,1,x)==fl(v+x); fma(v,0,x)==x)
//   out = (v > thr) ? v : 0.0f     (off-chain)

#define BB 16
#define SS 256
#define HH 128
#define NN 64
#define TT (SS * HH)

#define BLKROWS 8
#define NBLK (SS / BLKROWS)           // 32
#define ROWPAD 132
#define NGRP 32                       // (b, neuron-half)
#define NCHAIN NGRP
#define CHUNKS (BLKROWS * (HH / 4))   // 256 float4 per 8-row block

// 48KB static shared (partially used) -> occupancy capped at 4 CTAs/SM.
#define SMEM_FLOATS 12288             // 49152 bytes
#define SMEM_USED   (2 * 32 * ROWPAD) // 8448 floats actually used

static const size_t BSNH = (size_t)BB * SS * NN * HH;

__device__ float g_chk[NBLK][BB][NN];
__device__ int   g_flag[NBLK][NGRP][32];   // per-lane flags

__device__ __forceinline__ float set_le(float a, float b) {
    float r; asm("set.le.f32.f32 %0, %1, %2;" : "=f"(r) : "f"(a), "f"(b)); return r;
}
__device__ __forceinline__ void st_release(int* p, int v) {
    asm volatile("st.release.gpu.global.b32 [%0], %1;" :: "l"(p), "r"(v) : "memory");
}
__device__ __forceinline__ int ld_acquire(const int* p) {
    int v; asm volatile("ld.acquire.gpu.global.b32 %0, [%1];" : "=r"(v) : "l"(p) : "memory");
    return v;
}

#define CHAIN_STEP(XC) do {                 \
    float _m = set_le(v, thr);              \
    v = __fmaf_rn(v, _m, (XC));             \
} while (0)

#define OUT_STEP(XC, OC) do {               \
    float _m = set_le(v, thr);              \
    v = __fmaf_rn(v, _m, (XC));             \
    (OC) = (v > thr) ? v : 0.0f;            \
} while (0)

__global__ void lif_reset()
{
    int i = blockIdx.x * blockDim.x + threadIdx.x;
    if (i < NBLK * NGRP * 32) ((int*)g_flag)[i] = 0;
}

__global__ void __launch_bounds__(64, 1)
lif_fused(const float* __restrict__ x,       // [B, S, H]
          const float* __restrict__ thresh,  // [N]
          const float* __restrict__ acc0,    // [B, N]
          float* __restrict__ outbuf,        // outs | spikes
          int write_spikes)
{
    // Oversized on purpose: caps occupancy at 4 CTAs/SM (49152B each).
    __shared__ float smem_raw[SMEM_FLOATS];

    const int tid  = threadIdx.x;
    const int lane = tid & 31;

    if (blockIdx.x < NCHAIN) {
        // ================== CHAIN CTA ==================
        const int grp  = blockIdx.x;
        const int b    = grp >> 1;
        const int half = grp & 1;
        const int wid  = tid >> 5;

        float (*xsh)[BLKROWS * HH + 4] = (float (*)[BLKROWS * HH + 4])smem_raw;
        const float4* __restrict__ xg = (const float4*)(x + (size_t)b * TT);

        if (wid == 1) {                       // preload block 0
            #pragma unroll
            for (int i = lane; i < CHUNKS; i += 32)
                ((float4*)xsh[0])[i] = xg[i];
        }
        __syncthreads();

        if (wid == 0) {
            const int n = half * 32 + lane;
            const float thr = thresh[n];
            float v = acc0[b * NN + n];

            for (int blk = 0; blk < NBLK; ++blk) {
                // Publish checkpoint: plain store, then per-lane release
                // store of the flag (orders this thread's prior store).
                g_chk[blk][b][n] = v;
                st_release(&g_flag[blk][grp][lane], 1);

                const float4* xs4 = (const float4*)xsh[blk & 1];
                float4 xv = xs4[0];
                #pragma unroll 8
                for (int q = 0; q < CHUNKS; ++q) {
                    float4 xn = xs4[q + 1];   // broadcast LDS, pad-covered
                    CHAIN_STEP(xv.x); CHAIN_STEP(xv.y);
                    CHAIN_STEP(xv.z); CHAIN_STEP(xv.w);
                    xv = xn;
                }
                __syncthreads();              // block consumed; next staged
            }
        } else {
            for (int blk = 0; blk < NBLK; ++blk) {
                if (blk + 1 < NBLK) {
                    const float4* src = xg + (size_t)(blk + 1) * CHUNKS;
                    float4* dst = (float4*)xsh[(blk + 1) & 1];
                    #pragma unroll
                    for (int i = lane; i < CHUNKS; i += 32)
                        dst[i] = src[i];
                }
                __syncthreads();
            }
        }
    } else {
        // ================== OUTPUT CTA ==================
        const int cidx = blockIdx.x - NCHAIN;
        const int grp  = cidx & (NGRP - 1);   // grp varies fastest
        const int sblk = cidx >> 5;           // low blocks first
        const int b    = grp >> 1;
        const int n0   = (grp & 1) * 32;
        const int s0   = sblk * BLKROWS;

        float (*sbuf)[32 * ROWPAD] = (float (*)[32 * ROWPAD])smem_raw;

        if (tid < 32) {
            // -------- producer: per-lane acquire, then exact replay ------
            const int n = n0 + lane;
            while (ld_acquire(&g_flag[sblk][grp][lane]) == 0)
                __nanosleep(64);

            const float thr = thresh[n];
            float v = g_chk[sblk][b][n];

            const float4* __restrict__ xp =
                (const float4*)(x + (size_t)b * TT + (size_t)s0 * HH);

            float* const row0 = &sbuf[0][lane * ROWPAD];
            float* const row1 = &sbuf[1][lane * ROWPAD];

            for (int r = 0; r < BLKROWS; ++r) {
                float* rw = (r & 1) ? row1 : row0;
                const float4* xrow = xp + r * (HH / 4);
                #pragma unroll 8
                for (int q = 0; q < HH / 4; ++q) {
                    float4 xv = xrow[q];      // broadcast LDG (L2-hot)
                    float4 o;
                    OUT_STEP(xv.x, o.x); OUT_STEP(xv.y, o.y);
                    OUT_STEP(xv.z, o.z); OUT_STEP(xv.w, o.w);
                    *(float4*)&rw[q * 4] = o;
                }
                __syncthreads();              // row r staged
            }
        } else {
            // -------- flusher: transpose + spikes --------
            const int fl = tid - 32;
            float* __restrict__ outp = outbuf;
            float* __restrict__ spkp = outbuf + BSNH;

            for (int r = 0; r < BLKROWS; ++r) {
                __syncthreads();              // wait for row r
                const float* buf = sbuf[r & 1];
                const int s = s0 + r;
                size_t base = (((size_t)b * SS + s) * NN + n0) * HH + fl * 4;
                #pragma unroll 4
                for (int rr = 0; rr < 32; ++rr) {
                    float4 vv = *(const float4*)&buf[rr * ROWPAD + fl * 4];
                    *(float4*)&outp[base + (size_t)rr * HH] = vv;
                    if (write_spikes) {
                        float4 sp;
                        sp.x = (vv.x > 0.0f) ? 1.0f : 0.0f;
                        sp.y = (vv.y > 0.0f) ? 1.0f : 0.0f;
                        sp.z = (vv.z > 0.0f) ? 1.0f : 0.0f;
                        sp.w = (vv.w > 0.0f) ? 1.0f : 0.0f;
                        *(float4*)&spkp[base + (size_t)rr * HH] = sp;
                    }
                }
            }
        }
    }
}

extern "C" void kernel_launch(void* const* d_in, const int* in_sizes, int n_in,
                              void* d_out, int out_size)
{
    const float* x      = (const float*)d_in[0];  // [16, 256, 128] f32
    const float* thresh = (const float*)d_in[1];  // [64] f32
    const float* acc0   = (const float*)d_in[2];  // [16, 64] f32
    float* out = (float*)d_out;

    int write_spikes = ((size_t)out_size >= 2 * BSNH) ? 1 : 0;

    lif_reset<<<32, 1024>>>();
    lif_fused<<<NCHAIN + NGRP * NBLK, 64>>>(x, thresh, acc0, out, write_spikes);
}